// round 2
// baseline (speedup 1.0000x reference)
#include <cuda_runtime.h>

#define NT   256
#define ROWS 8
#define IT   4

typedef unsigned long long u64;

__device__ double       g_sum;   // zero-initialized; reset by last block each run
__device__ double       g_adj;
__device__ unsigned int g_cnt;   // monotonic arrival counter (mod gridsize)

static __device__ __forceinline__ u64 pk(float lo, float hi) {
    u64 r; asm("mov.b64 %0,{%1,%2};" : "=l"(r) : "f"(lo), "f"(hi)); return r;
}
static __device__ __forceinline__ void upk(u64 v, float& lo, float& hi) {
    asm("mov.b64 {%0,%1},%2;" : "=f"(lo), "=f"(hi) : "l"(v));
}
static __device__ __forceinline__ u64 fma2(u64 a, u64 b, u64 c) {
    u64 d; asm("fma.rn.f32x2 %0,%1,%2,%3;" : "=l"(d) : "l"(a), "l"(b), "l"(c)); return d;
}
static __device__ __forceinline__ u64 add2(u64 a, u64 b) {
    u64 d; asm("add.rn.f32x2 %0,%1,%2;" : "=l"(d) : "l"(a), "l"(b)); return d;
}
static __device__ __forceinline__ u64 mul2(u64 a, u64 b) {
    u64 d; asm("mul.rn.f32x2 %0,%1,%2;" : "=l"(d) : "l"(a), "l"(b)); return d;
}
static __device__ __forceinline__ float sqa(float x) {
    float y; asm("sqrt.approx.f32 %0,%1;" : "=f"(y) : "f"(x)); return y;
}

extern __shared__ float4 s_pts[];  // [0,N): preds {x,y,z,|p|^2}; [N,2N): targets

__global__ void __launch_bounds__(NT, 2)
loss_kernel(const float* __restrict__ preds,
            const float* __restrict__ targets,
            const float* __restrict__ adj,
            float* __restrict__ out,
            int N)
{
    const int b    = blockIdx.y;
    const int row0 = blockIdx.x * ROWS;
    float4* sp = s_pts;
    float4* st = s_pts + N;

    // Stage points + squared norms into SMEM
    {
        const float* pb = preds   + (size_t)b * N * 3;
        const float* tb = targets + (size_t)b * N * 3;
        for (int k = threadIdx.x; k < N; k += NT) {
            float x = pb[3*k], y = pb[3*k+1], z = pb[3*k+2];
            sp[k] = make_float4(x, y, z, fmaf(x, x, fmaf(y, y, z*z)));
            float u = tb[3*k], v = tb[3*k+1], w = tb[3*k+2];
            st[k] = make_float4(u, v, w, fmaf(u, u, fmaf(v, v, w*w)));
        }
    }
    __syncthreads();

    u64 acc0 = 0ull, acc1 = 0ull, accA = 0ull;   // packed (0.f,0.f)
    const u64 NEG2 = pk(-2.f, -2.f);
    const int N4 = N >> 2;
    const float* adjB = adj + (size_t)b * N * N;

    for (int ig = 0; ig < ROWS; ig += IT) {
        const int rbase = row0 + ig;
        // Row constants, broadcast-packed: (-2*x,-2*x),(-2*y,..),(-2*z,..),(w,w)
        u64 RP[IT][4], RT[IT][4];
        #pragma unroll
        for (int r = 0; r < IT; r++) {
            float4 P = sp[rbase + r];
            RP[r][0] = pk(-2.f*P.x, -2.f*P.x);
            RP[r][1] = pk(-2.f*P.y, -2.f*P.y);
            RP[r][2] = pk(-2.f*P.z, -2.f*P.z);
            RP[r][3] = pk(P.w, P.w);
            float4 T = st[rbase + r];
            RT[r][0] = pk(-2.f*T.x, -2.f*T.x);
            RT[r][1] = pk(-2.f*T.y, -2.f*T.y);
            RT[r][2] = pk(-2.f*T.z, -2.f*T.z);
            RT[r][3] = pk(T.w, T.w);
        }

        const float4* adjR = (const float4*)(adjB + (size_t)rbase * N);

        for (int jv = threadIdx.x; jv < N4; jv += NT) {
            float4 p0 = sp[4*jv], p1 = sp[4*jv+1], p2 = sp[4*jv+2], p3 = sp[4*jv+3];
            float4 t0 = st[4*jv], t1 = st[4*jv+1], t2 = st[4*jv+2], t3 = st[4*jv+3];
            // pack j-pairs (q0,q1) and (q2,q3)
            u64 pX0 = pk(p0.x,p1.x), pX1 = pk(p2.x,p3.x);
            u64 pY0 = pk(p0.y,p1.y), pY1 = pk(p2.y,p3.y);
            u64 pZ0 = pk(p0.z,p1.z), pZ1 = pk(p2.z,p3.z);
            u64 pW0 = pk(p0.w,p1.w), pW1 = pk(p2.w,p3.w);
            u64 tX0 = pk(t0.x,t1.x), tX1 = pk(t2.x,t3.x);
            u64 tY0 = pk(t0.y,t1.y), tY1 = pk(t2.y,t3.y);
            u64 tZ0 = pk(t0.z,t1.z), tZ1 = pk(t2.z,t3.z);
            u64 tW0 = pk(t0.w,t1.w), tW1 = pk(t2.w,t3.w);

            #pragma unroll
            for (int r = 0; r < IT; r++) {
                float4 a = __ldcs(adjR + (size_t)r * N4 + jv);
                u64 a0 = pk(a.x, a.y), a1 = pk(a.z, a.w);

                // sq = w_i + w_j - 2*dot  (packed over 2 j's)
                u64 sqp0 = fma2(RP[r][0], pX0, fma2(RP[r][1], pY0, fma2(RP[r][2], pZ0, add2(RP[r][3], pW0))));
                u64 sqt0 = fma2(RT[r][0], tX0, fma2(RT[r][1], tY0, fma2(RT[r][2], tZ0, add2(RT[r][3], tW0))));
                u64 pr0  = mul2(sqp0, sqt0);
                u64 s0   = add2(sqp0, sqt0);
                float g0, g1; upk(pr0, g0, g1);
                u64 rt0 = pk(sqa(fmaxf(g0, 0.f)), sqa(fmaxf(g1, 0.f)));
                // d2 = sqp + sqt - 2*sqrt(sqp*sqt) = (dp-dt)^2 ; adj in {0,1}
                u64 d0  = fma2(NEG2, rt0, s0);
                acc0 = fma2(d0, a0, acc0);

                u64 sqp1 = fma2(RP[r][0], pX1, fma2(RP[r][1], pY1, fma2(RP[r][2], pZ1, add2(RP[r][3], pW1))));
                u64 sqt1 = fma2(RT[r][0], tX1, fma2(RT[r][1], tY1, fma2(RT[r][2], tZ1, add2(RT[r][3], tW1))));
                u64 pr1  = mul2(sqp1, sqt1);
                u64 s1   = add2(sqp1, sqt1);
                float h0, h1; upk(pr1, h0, h1);
                u64 rt1 = pk(sqa(fmaxf(h0, 0.f)), sqa(fmaxf(h1, 0.f)));
                u64 d1  = fma2(NEG2, rt1, s1);
                acc1 = fma2(d1, a1, acc1);

                accA = add2(accA, add2(a0, a1));
            }
        }
    }

    // collapse packed accumulators
    float a0l, a0h, a1l, a1h, nal, nah;
    upk(acc0, a0l, a0h); upk(acc1, a1l, a1h); upk(accA, nal, nah);
    float acc  = (a0l + a0h) + (a1l + a1h);
    float accN = nal + nah;

    // warp reduce
    #pragma unroll
    for (int off = 16; off > 0; off >>= 1) {
        acc  += __shfl_down_sync(0xffffffffu, acc,  off);
        accN += __shfl_down_sync(0xffffffffu, accN, off);
    }
    __shared__ float2 wsum[NT / 32];
    int wid = threadIdx.x >> 5, lane = threadIdx.x & 31;
    if (lane == 0) wsum[wid] = make_float2(acc, accN);
    __syncthreads();
    if (wid == 0) {
        float2 v = (lane < NT / 32) ? wsum[lane] : make_float2(0.f, 0.f);
        #pragma unroll
        for (int off = 4; off > 0; off >>= 1) {
            v.x += __shfl_down_sync(0xffffffffu, v.x, off);
            v.y += __shfl_down_sync(0xffffffffu, v.y, off);
        }
        if (lane == 0) {
            atomicAdd(&g_sum, (double)v.x);
            atomicAdd(&g_adj, (double)v.y);
            __threadfence();
            unsigned int nb  = gridDim.x * gridDim.y;
            unsigned int old = atomicAdd(&g_cnt, 1u);
            if (old % nb == nb - 1u) {           // last block of this run
                __threadfence();
                double s = atomicAdd(&g_sum, 0.0);
                double n = atomicAdd(&g_adj, 0.0);
                out[0] = (float)(s / n);
                g_sum = 0.0;                      // reset for next graph replay
                g_adj = 0.0;
            }
        }
    }
}

extern "C" void kernel_launch(void* const* d_in, const int* in_sizes, int n_in,
                              void* d_out, int out_size)
{
    const float* preds   = (const float*)d_in[0];
    const float* targets = (const float*)d_in[1];
    const float* adj     = (const float*)d_in[2];

    long long psz   = in_sizes[0];          // B*N*3
    long long adjsz = in_sizes[2];          // B*N*N
    int N = (int)(3LL * adjsz / psz);       // 2048
    int B = (int)(psz / (3LL * N));         // 8

    size_t smem = (size_t)2 * N * sizeof(float4);  // 64KB
    cudaFuncSetAttribute(loss_kernel, cudaFuncAttributeMaxDynamicSharedMemorySize, (int)smem);

    dim3 grid(N / ROWS, B);
    loss_kernel<<<grid, NT, smem>>>(preds, targets, adj, (float*)d_out, N);
}

// round 3
// speedup vs baseline: 1.0157x; 1.0157x over previous
#include <cuda_runtime.h>

#define NT     256
#define ROWS   16
#define IT     4
#define JSPLIT 2

__device__ double       g_sum;   // zero-init; reset by last block each run
__device__ double       g_adj;
__device__ unsigned int g_cnt;   // monotonic arrival counter (mod gridsize)

static __device__ __forceinline__ float sqa(float x) {
    float y; asm("sqrt.approx.f32 %0,%1;" : "=f"(y) : "f"(x)); return y;
}

extern __shared__ float4 s_pts[];  // [0,NH): preds {x,y,z,|p|^2}; [NH,2NH): targets

__global__ void __launch_bounds__(NT, 3)
loss_kernel(const float* __restrict__ preds,
            const float* __restrict__ targets,
            const float* __restrict__ adj,
            float* __restrict__ out,
            int N)
{
    const int b    = blockIdx.z;
    const int jh   = blockIdx.y;
    const int row0 = blockIdx.x * ROWS;
    const int NH   = N / JSPLIT;
    const int j0   = jh * NH;

    float4* sp = s_pts;
    float4* st = s_pts + NH;

    // Stage this CTA's j-half of points + squared norms into SMEM (32KB)
    {
        const float* pb = preds   + ((size_t)b * N + j0) * 3;
        const float* tb = targets + ((size_t)b * N + j0) * 3;
        for (int k = threadIdx.x; k < NH; k += NT) {
            float x = pb[3*k], y = pb[3*k+1], z = pb[3*k+2];
            sp[k] = make_float4(x, y, z, fmaf(x, x, fmaf(y, y, z*z)));
            float u = tb[3*k], v = tb[3*k+1], w = tb[3*k+2];
            st[k] = make_float4(u, v, w, fmaf(u, u, fmaf(v, v, w*w)));
        }
    }
    __syncthreads();

    float acc = 0.f, accA = 0.f;
    const int NH4 = NH >> 2;
    const int N4  = N >> 2;
    const float* adjB = adj + (size_t)b * N * N;

    for (int ig = 0; ig < ROWS; ig += IT) {
        const int rbase = row0 + ig;

        // Row constants from global (broadcast loads, L1-cached), pre-scaled by -2
        float4 P[IT], T[IT];
        #pragma unroll
        for (int r = 0; r < IT; r++) {
            const float* pr = preds   + ((size_t)b * N + rbase + r) * 3;
            const float* tr = targets + ((size_t)b * N + rbase + r) * 3;
            float x = pr[0], y = pr[1], z = pr[2];
            P[r] = make_float4(-2.f*x, -2.f*y, -2.f*z, fmaf(x, x, fmaf(y, y, z*z)));
            float u = tr[0], v = tr[1], w = tr[2];
            T[r] = make_float4(-2.f*u, -2.f*v, -2.f*w, fmaf(u, u, fmaf(v, v, w*w)));
        }

        const float4* adjR = (const float4*)(adjB + (size_t)rbase * N + j0);

        for (int jv = threadIdx.x; jv < NH4; jv += NT) {
            float4 pj[4], tj[4];
            #pragma unroll
            for (int q = 0; q < 4; q++) { pj[q] = sp[4*jv + q]; tj[q] = st[4*jv + q]; }

            #pragma unroll
            for (int r = 0; r < IT; r++) {
                float4 a = __ldcs(adjR + (size_t)r * N4 + jv);
                float av[4] = {a.x, a.y, a.z, a.w};
                #pragma unroll
                for (int q = 0; q < 4; q++) {
                    // sq dist via norm form; -2 pre-folded into P/T row constants
                    float sqp = fmaf(P[r].x, pj[q].x,
                                fmaf(P[r].y, pj[q].y,
                                fmaf(P[r].z, pj[q].z, P[r].w + pj[q].w)));
                    float sqt = fmaf(T[r].x, tj[q].x,
                                fmaf(T[r].y, tj[q].y,
                                fmaf(T[r].z, tj[q].z, T[r].w + tj[q].w)));
                    // (sqrt(a)-sqrt(b))^2 = a + b - 2*sqrt(a*b): one MUFU/element
                    float rt = sqa(fmaxf(sqp * sqt, 0.f));
                    float d2 = fmaf(-2.f, rt, sqp + sqt);
                    acc = fmaf(d2, av[q], acc);   // adj in {0,1}
                }
                accA += (a.x + a.y) + (a.z + a.w);
            }
        }
    }

    // warp reduce
    #pragma unroll
    for (int off = 16; off > 0; off >>= 1) {
        acc  += __shfl_down_sync(0xffffffffu, acc,  off);
        accA += __shfl_down_sync(0xffffffffu, accA, off);
    }
    __shared__ float2 wsum[NT / 32];
    int wid = threadIdx.x >> 5, lane = threadIdx.x & 31;
    if (lane == 0) wsum[wid] = make_float2(acc, accA);
    __syncthreads();
    if (wid == 0) {
        float2 v = (lane < NT / 32) ? wsum[lane] : make_float2(0.f, 0.f);
        #pragma unroll
        for (int off = 4; off > 0; off >>= 1) {
            v.x += __shfl_down_sync(0xffffffffu, v.x, off);
            v.y += __shfl_down_sync(0xffffffffu, v.y, off);
        }
        if (lane == 0) {
            atomicAdd(&g_sum, (double)v.x);
            atomicAdd(&g_adj, (double)v.y);
            __threadfence();
            unsigned int nb  = gridDim.x * gridDim.y * gridDim.z;
            unsigned int old = atomicAdd(&g_cnt, 1u);
            if (old % nb == nb - 1u) {            // last block of this run
                __threadfence();
                double s = atomicAdd(&g_sum, 0.0);
                double n = atomicAdd(&g_adj, 0.0);
                out[0] = (float)(s / n);
                g_sum = 0.0;                       // reset for next graph replay
                g_adj = 0.0;
            }
        }
    }
}

extern "C" void kernel_launch(void* const* d_in, const int* in_sizes, int n_in,
                              void* d_out, int out_size)
{
    const float* preds   = (const float*)d_in[0];
    const float* targets = (const float*)d_in[1];
    const float* adj     = (const float*)d_in[2];

    long long psz   = in_sizes[0];          // B*N*3
    long long adjsz = in_sizes[2];          // B*N*N
    int N = (int)(3LL * adjsz / psz);       // 2048
    int B = (int)(psz / (3LL * N));         // 8

    size_t smem = (size_t)2 * (N / JSPLIT) * sizeof(float4);  // 32KB
    cudaFuncSetAttribute(loss_kernel, cudaFuncAttributeMaxDynamicSharedMemorySize, (int)smem);

    dim3 grid(N / ROWS, JSPLIT, B);
    loss_kernel<<<grid, NT, smem>>>(preds, targets, adj, (float*)d_out, N);
}

// round 4
// speedup vs baseline: 1.0419x; 1.0258x over previous
#include <cuda_runtime.h>

#define NT     256
#define ROWS   16
#define IT     4
#define JSPLIT 2

__device__ double       g_sum;   // zero-init; reset by last block each run
__device__ double       g_adj;
__device__ unsigned int g_cnt;   // monotonic arrival counter (mod gridsize)

static __device__ __forceinline__ float sqa(float x) {
    float y; asm("sqrt.approx.f32 %0,%1;" : "=f"(y) : "f"(x)); return y;
}

extern __shared__ float s_raw[];   // 8 SoA arrays of NH floats each (conflict-free LDS.128)

__global__ void __launch_bounds__(NT, 3)
loss_kernel(const float* __restrict__ preds,
            const float* __restrict__ targets,
            const float* __restrict__ adj,
            float* __restrict__ out,
            int N)
{
    const int b    = blockIdx.z;
    const int jh   = blockIdx.y;
    const int row0 = blockIdx.x * ROWS;
    const int NH   = N / JSPLIT;
    const int j0   = jh * NH;

    float* spx = s_raw;           float* spy = spx + NH;
    float* spz = spy + NH;        float* spw = spz + NH;
    float* stx = spw + NH;        float* sty = stx + NH;
    float* stz = sty + NH;        float* stw = stz + NH;

    // Stage this CTA's j-half of points + squared norms into SMEM (SoA, 32KB)
    {
        const float* pb = preds   + ((size_t)b * N + j0) * 3;
        const float* tb = targets + ((size_t)b * N + j0) * 3;
        for (int k = threadIdx.x; k < NH; k += NT) {
            float x = pb[3*k], y = pb[3*k+1], z = pb[3*k+2];
            spx[k] = x; spy[k] = y; spz[k] = z; spw[k] = fmaf(x, x, fmaf(y, y, z*z));
            float u = tb[3*k], v = tb[3*k+1], w = tb[3*k+2];
            stx[k] = u; sty[k] = v; stz[k] = w; stw[k] = fmaf(u, u, fmaf(v, v, w*w));
        }
    }
    __syncthreads();

    float acc = 0.f, accA = 0.f;
    const int NH4 = NH >> 2;
    const int N4  = N >> 2;
    const float* adjB = adj + (size_t)b * N * N;

    for (int ig = 0; ig < ROWS; ig += IT) {
        const int rbase = row0 + ig;

        // Row constants from global (broadcast loads), pre-scaled by -2
        float4 P[IT], T[IT];
        #pragma unroll
        for (int r = 0; r < IT; r++) {
            const float* pr = preds   + ((size_t)b * N + rbase + r) * 3;
            const float* tr = targets + ((size_t)b * N + rbase + r) * 3;
            float x = pr[0], y = pr[1], z = pr[2];
            P[r] = make_float4(-2.f*x, -2.f*y, -2.f*z, fmaf(x, x, fmaf(y, y, z*z)));
            float u = tr[0], v = tr[1], w = tr[2];
            T[r] = make_float4(-2.f*u, -2.f*v, -2.f*w, fmaf(u, u, fmaf(v, v, w*w)));
        }

        const float4* adjR = (const float4*)(adjB + (size_t)rbase * N + j0);

        for (int jv = threadIdx.x; jv < NH4; jv += NT) {
            // SoA vector loads: lane stride 16B -> conflict-free LDS.128
            float4 jpx = ((const float4*)spx)[jv];
            float4 jpy = ((const float4*)spy)[jv];
            float4 jpz = ((const float4*)spz)[jv];
            float4 jpw = ((const float4*)spw)[jv];
            float4 jtx = ((const float4*)stx)[jv];
            float4 jty = ((const float4*)sty)[jv];
            float4 jtz = ((const float4*)stz)[jv];
            float4 jtw = ((const float4*)stw)[jv];
            const float px_[4] = {jpx.x, jpx.y, jpx.z, jpx.w};
            const float py_[4] = {jpy.x, jpy.y, jpy.z, jpy.w};
            const float pz_[4] = {jpz.x, jpz.y, jpz.z, jpz.w};
            const float pw_[4] = {jpw.x, jpw.y, jpw.z, jpw.w};
            const float tx_[4] = {jtx.x, jtx.y, jtx.z, jtx.w};
            const float ty_[4] = {jty.x, jty.y, jty.z, jty.w};
            const float tz_[4] = {jtz.x, jtz.y, jtz.z, jtz.w};
            const float tw_[4] = {jtw.x, jtw.y, jtw.z, jtw.w};

            #pragma unroll
            for (int r = 0; r < IT; r++) {
                float4 a = __ldcs(adjR + (size_t)r * N4 + jv);
                float av[4] = {a.x, a.y, a.z, a.w};
                #pragma unroll
                for (int q = 0; q < 4; q++) {
                    float sqp = fmaf(P[r].x, px_[q],
                                fmaf(P[r].y, py_[q],
                                fmaf(P[r].z, pz_[q], P[r].w + pw_[q])));
                    float sqt = fmaf(T[r].x, tx_[q],
                                fmaf(T[r].y, ty_[q],
                                fmaf(T[r].z, tz_[q], T[r].w + tw_[q])));
                    // (sqrt(a)-sqrt(b))^2 = a + b - 2*sqrt(a*b): one MUFU/element
                    float rt = sqa(fmaxf(sqp * sqt, 0.f));
                    float d2 = fmaf(-2.f, rt, sqp + sqt);
                    acc = fmaf(d2, av[q], acc);   // adj in {0,1}
                }
                accA += (a.x + a.y) + (a.z + a.w);
            }
        }
    }

    // warp reduce
    #pragma unroll
    for (int off = 16; off > 0; off >>= 1) {
        acc  += __shfl_down_sync(0xffffffffu, acc,  off);
        accA += __shfl_down_sync(0xffffffffu, accA, off);
    }
    __shared__ float2 wsum[NT / 32];
    int wid = threadIdx.x >> 5, lane = threadIdx.x & 31;
    if (lane == 0) wsum[wid] = make_float2(acc, accA);
    __syncthreads();
    if (wid == 0) {
        float2 v = (lane < NT / 32) ? wsum[lane] : make_float2(0.f, 0.f);
        #pragma unroll
        for (int off = 4; off > 0; off >>= 1) {
            v.x += __shfl_down_sync(0xffffffffu, v.x, off);
            v.y += __shfl_down_sync(0xffffffffu, v.y, off);
        }
        if (lane == 0) {
            atomicAdd(&g_sum, (double)v.x);
            atomicAdd(&g_adj, (double)v.y);
            __threadfence();
            unsigned int nb  = gridDim.x * gridDim.y * gridDim.z;
            unsigned int old = atomicAdd(&g_cnt, 1u);
            if (old % nb == nb - 1u) {            // last block of this run
                __threadfence();
                double s = atomicAdd(&g_sum, 0.0);
                double n = atomicAdd(&g_adj, 0.0);
                out[0] = (float)(s / n);
                g_sum = 0.0;                       // reset for next graph replay
                g_adj = 0.0;
            }
        }
    }
}

extern "C" void kernel_launch(void* const* d_in, const int* in_sizes, int n_in,
                              void* d_out, int out_size)
{
    const float* preds   = (const float*)d_in[0];
    const float* targets = (const float*)d_in[1];
    const float* adj     = (const float*)d_in[2];

    long long psz   = in_sizes[0];          // B*N*3
    long long adjsz = in_sizes[2];          // B*N*N
    int N = (int)(3LL * adjsz / psz);       // 2048
    int B = (int)(psz / (3LL * N));         // 8

    size_t smem = (size_t)8 * (N / JSPLIT) * sizeof(float);  // 32KB
    cudaFuncSetAttribute(loss_kernel, cudaFuncAttributeMaxDynamicSharedMemorySize, (int)smem);

    dim3 grid(N / ROWS, JSPLIT, B);
    loss_kernel<<<grid, NT, smem>>>(preds, targets, adj, (float*)d_out, N);
}